// round 5
// baseline (speedup 1.0000x reference)
#include <cuda_runtime.h>

#define NB 16384

enum { L_E1 = 0, L_E2, L_E3, L_E4, L_D1, L_D2, L_D3, L_D4 };

// Output layout (concatenated flat outputs, float32):
//   zq3   : [0, 8388608)            (N,512,1)
//   x_hat : [8388608, 50331648)     (N,256,10)
//   idx   : [50331648, 50348032)    (N,1) as float
//   emb_loss, qq_loss, ac_loss : 3 scalars
#define ZQ_OFF   0
#define XHAT_OFF 8388608
#define IDX_OFF  50331648
#define EMB_OFF  50348032

// ---- scratch (device globals; no allocation allowed) ----
__device__ float g_h1[NB * 1280];   // (N,10,128) encoder conv1 out (post-relu)
__device__ float g_h2[NB * 1024];   // (N,4,256)  encoder conv2 out (post-relu)
__device__ float g_h3[NB * 512];    // (N,512)    encoder conv3 out (post-relu)
__device__ float g_z [NB * 512];    // (N,512)    z_e
__device__ float g_zn[NB];          // |z|^2 per row, correctly-rounded fp32
__device__ float g_d1[NB * 512];    // (N,512)    decoder convT1 out (post-relu)
__device__ float g_d2[NB * 1024];   // (N, s(4), i(256)) decoder convT2 out (post-relu)
__device__ float g_y [NB * 1280];   // (N, o(128), t(10)) convT3 accumulator (pre-relu)
__device__ int   g_idx[NB];

// transformed weights: uniform [K][N] layout
__device__ float g_W1t[256 * 128];
__device__ float g_W2t[512 * 256];
__device__ float g_W3t[1024 * 512];
__device__ float g_W4t[512 * 512];
__device__ float g_V2t[512 * 1024];
__device__ float g_CBt[512 * 1024]; // codebook transposed (k, e)
__device__ float g_cbn[1024];       // |e|^2 (fp64-accumulated, rounded to fp32)
__device__ double g_loss;

// ---------------------------------------------------------------------------
// weight pre-transforms (cheap, a few MB, run every launch)
// ---------------------------------------------------------------------------
__global__ void prep_kernel(const float* __restrict__ ew1, const float* __restrict__ ew2,
                            const float* __restrict__ ew3, const float* __restrict__ ew4,
                            const float* __restrict__ cb,  const float* __restrict__ dw2)
{
    int e = blockIdx.x * blockDim.x + threadIdx.x;   // 524288 threads
    if (e < 256 * 128)  { int k = e >> 7,  o = e & 127;  g_W1t[e] = ew1[o * 256 + k]; }
    if (e < 512 * 256)  { int k = e >> 8,  o = e & 255;  g_W2t[e] = ew2[o * 512 + (k & 127) * 4 + (k >> 7)]; }
    if (e < 1024 * 512) { int k = e >> 9,  o = e & 511;  g_W3t[e] = ew3[o * 1024 + (k & 255) * 4 + (k >> 8)]; }
    if (e < 512 * 512)  { int k = e >> 9,  o = e & 511;  g_W4t[e] = ew4[o * 512 + k]; }
    if (e < 512 * 1024) { int k = e >> 10, c = e & 1023; g_CBt[e] = cb[c * 512 + k]; }
    if (e < 512 * 1024) { int k = e >> 10, j = e & 1023; g_V2t[e] = dw2[k * 1024 + (j & 255) * 4 + (j >> 8)]; }
    if (e < 1024) {
        // |e|^2: fp32 elementwise square (as the reference does), fp64 sum, round once.
        double s = 0.0;
        for (int k = 0; k < 512; k++) { float v = cb[e * 512 + k]; s += (double)(v * v); }
        g_cbn[e] = (float)s;
    }
    if (e == 0) g_loss = 0.0;
}

// ---------------------------------------------------------------------------
// per-row |z|^2: fp32 squares, fp64 accumulate, single rounding to fp32
// ---------------------------------------------------------------------------
__global__ void rownorm_kernel()
{
    int warp = (blockIdx.x * blockDim.x + threadIdx.x) >> 5;  // one warp per row
    int lane = threadIdx.x & 31;
    if (warp >= NB) return;
    const float* zr = g_z + warp * 512;
    double s = 0.0;
    for (int k = lane; k < 512; k += 32) {
        float v = zr[k];
        s += (double)(v * v);
    }
#pragma unroll
    for (int o = 16; o > 0; o >>= 1)
        s += __shfl_down_sync(0xffffffffu, s, o);
    if (lane == 0) g_zn[warp] = (float)s;
}

// ---------------------------------------------------------------------------
// per-layer A-tile element loads (im2col folded in)
// ---------------------------------------------------------------------------
template <int L>
__device__ __forceinline__ float ldA(const float* __restrict__ A, int m, int k, int sarg)
{
    if constexpr (L == L_E1) {           // x (N,256,10), m = n*10+t
        int n = m / 10, t = m - n * 10;
        return A[n * 2560 + k * 10 + t];
    } else if constexpr (L == L_E2) {    // h1 (N,10,128), m = n*4+s, k = kk*128+i
        int n = m >> 2, s = m & 3;
        return A[(n * 10 + 2 * s + (k >> 7)) * 128 + (k & 127)];
    } else if constexpr (L == L_E3) {
        return A[m * 1024 + k];
    } else if constexpr (L == L_D3) {    // d2 (N, s, i): slice sarg
        return A[m * 1024 + sarg * 256 + k];
    } else if constexpr (L == L_D4) {    // y (N,o,t) with deferred relu, m = n*10+t, k = o
        int n = m / 10, t = m - n * 10;
        return fmaxf(A[n * 1280 + k * 10 + t], 0.0f);
    } else {                             // E4, D1, D2: (N,512)
        return A[m * 512 + k];
    }
}

// ===========================================================================
// fp32 SGEMM core: 128x128 block tile, 128 threads, 8x16 per thread, BK=8,
// scalar FFMA, float4 smem fragments, register-prefetch double buffering.
// Thread grid: trow = tid>>3 (0..15) -> rows trow*4+{0..3} and +64
//              tcol = tid&7  (0..7)  -> cols tcol*8+{0..7} and +64
// Per warp per kk: 6 LDS.128 feed 128 FFMA  (wf/FFMA = 0.1875)
// ===========================================================================
#define GEMM_CORE_DECLS                                                        \
    __shared__ __align__(16) float As[2][8][128];                              \
    __shared__ __align__(16) float Bs[2][8][128];                              \
    const int tid  = threadIdx.x;                                              \
    const int trow = tid >> 3;                                                 \
    const int tcol = tid & 7;                                                  \
    const int brow = tid >> 4;   /* 0..7  */                                   \
    const int bcol = (tid & 15) * 8;

// one K-sweep over [0,K): A via ldA<L>, B row-major [K][NT]
template <int L, int K, int NT>
__device__ __forceinline__ void gemm_sweep(
    const float* __restrict__ A, const float* __restrict__ B,
    int m0, int n0, int sarg,
    float As[2][8][128], float Bs[2][8][128],
    int tid, int trow, int tcol, int brow, int bcol,
    float acc[8][16])
{
    // prologue: tile 0 straight to smem buffer 0
#pragma unroll
    for (int i = 0; i < 8; i++)
        As[0][i][tid] = ldA<L>(A, m0 + tid, i, sarg);
    *(float4*)&Bs[0][brow][bcol]     = *(const float4*)&B[brow * NT + n0 + bcol];
    *(float4*)&Bs[0][brow][bcol + 4] = *(const float4*)&B[brow * NT + n0 + bcol + 4];
    __syncthreads();

    int buf = 0;
#pragma unroll 1
    for (int k0 = 0; k0 < K; k0 += 8) {
        float  ar[8];
        float4 br0, br1;
        const bool more = (k0 + 8 < K);
        if (more) {
#pragma unroll
            for (int i = 0; i < 8; i++)
                ar[i] = ldA<L>(A, m0 + tid, k0 + 8 + i, sarg);
            br0 = *(const float4*)&B[(k0 + 8 + brow) * NT + n0 + bcol];
            br1 = *(const float4*)&B[(k0 + 8 + brow) * NT + n0 + bcol + 4];
        }
#pragma unroll
        for (int kk = 0; kk < 8; kk++) {
            float a[8], b[16];
            *(float4*)&a[0]  = *(const float4*)&As[buf][kk][trow * 4];
            *(float4*)&a[4]  = *(const float4*)&As[buf][kk][trow * 4 + 64];
            *(float4*)&b[0]  = *(const float4*)&Bs[buf][kk][tcol * 8];
            *(float4*)&b[4]  = *(const float4*)&Bs[buf][kk][tcol * 8 + 4];
            *(float4*)&b[8]  = *(const float4*)&Bs[buf][kk][tcol * 8 + 64];
            *(float4*)&b[12] = *(const float4*)&Bs[buf][kk][tcol * 8 + 68];
#pragma unroll
            for (int ii = 0; ii < 8; ii++)
#pragma unroll
                for (int jj = 0; jj < 16; jj++)
                    acc[ii][jj] = fmaf(a[ii], b[jj], acc[ii][jj]);
        }
        if (more) {
#pragma unroll
            for (int i = 0; i < 8; i++)
                As[buf ^ 1][i][tid] = ar[i];
            *(float4*)&Bs[buf ^ 1][brow][bcol]     = br0;
            *(float4*)&Bs[buf ^ 1][brow][bcol + 4] = br1;
            __syncthreads();
            buf ^= 1;
        }
    }
}

// row/col mapping: ii -> m offset, jj -> col offset
#define ACC_ROW(ii) (trow * 4 + ((ii) & 3) + (((ii) & 4) ? 64 : 0))
#define ACC_COL(jj) (tcol * 8 + ((jj) & 7) + (((jj) & 8) ? 64 : 0))

// ---------------------------------------------------------------------------
// generic fp32 SGEMM with per-layer epilogue
// ---------------------------------------------------------------------------
template <int L>
__global__ __launch_bounds__(128, 2)
void gemm_k(const float* __restrict__ extA, const float* __restrict__ extB,
            const float* __restrict__ bias, float* __restrict__ extC, int sarg)
{
    constexpr int K  = (L == L_E1) ? 256 : (L == L_E2) ? 512 : (L == L_E3) ? 1024 :
                       (L == L_E4) ? 512 : (L == L_D1) ? 512 : (L == L_D2) ? 512 :
                       (L == L_D3) ? 256 : 128;
    constexpr int NT = (L == L_E1) ? 128 : (L == L_E2) ? 256 : (L == L_E3) ? 512 :
                       (L == L_E4) ? 512 : (L == L_D1) ? 512 : (L == L_D2) ? 1024 :
                       (L == L_D3) ? 512 : 256;
    constexpr bool RELU = (L == L_E1 || L == L_E2 || L == L_E3 || L == L_D1 || L == L_D2);

    const float* A = extA;
    const float* B = extB;
    float* C = extC;
    if constexpr (L == L_E1) { B = g_W1t; C = g_h1; }
    if constexpr (L == L_E2) { A = g_h1; B = g_W2t; C = g_h2; }
    if constexpr (L == L_E3) { A = g_h2; B = g_W3t; C = g_h3; }
    if constexpr (L == L_E4) { A = g_h3; B = g_W4t; C = g_z; }
    if constexpr (L == L_D1) { C = g_d1; }
    if constexpr (L == L_D2) { A = g_d1; B = g_V2t; C = g_d2; }
    if constexpr (L == L_D3) { A = g_d2; C = g_y; }
    if constexpr (L == L_D4) { A = g_y; }

    GEMM_CORE_DECLS
    const int m0 = blockIdx.y * 128;
    const int n0 = blockIdx.x * 128;

    float acc[8][16];
#pragma unroll
    for (int i = 0; i < 8; i++)
#pragma unroll
        for (int j = 0; j < 16; j++) acc[i][j] = 0.0f;

    gemm_sweep<L, K, NT>(A, B, m0, n0, sarg, As, Bs, tid, trow, tcol, brow, bcol, acc);

    // epilogue
#pragma unroll
    for (int ii = 0; ii < 8; ii++) {
        const int m = m0 + ACC_ROW(ii);
#pragma unroll
        for (int jj = 0; jj < 16; jj++) {
            const int col = n0 + ACC_COL(jj);
            float v = acc[ii][jj];
            if constexpr (L == L_D3) {
                // scatter-add into y (N, o, t): col = o*4 + kk, t = 2s + kk
                C[m * 1280 + (col >> 2) * 10 + 2 * sarg + (col & 3)] += v;
            } else if constexpr (L == L_D4) {
                int n = m / 10, t = m - n * 10;
                C[n * 2560 + col * 10 + t] = v + bias[col];
            } else {
                v += bias[(L == L_D2) ? (col & 255) : col];
                if (RELU) v = fmaxf(v, 0.0f);
                C[m * NT + col] = v;
            }
        }
    }
}

// ---------------------------------------------------------------------------
// VQ: per-row argmin of d = fl( fl(|z|^2 + |e|^2) - 2 z.e )  — exact fp32
// replication of the reference's rounding so near-tie resolution matches.
// ---------------------------------------------------------------------------
__global__ __launch_bounds__(128, 2)
void vq_kernel()
{
    GEMM_CORE_DECLS
    __shared__ float sd[128][8];
    __shared__ int   si[128][8];

    const int m0 = blockIdx.x * 128;

    float s1v[8];
#pragma unroll
    for (int ii = 0; ii < 8; ii++)
        s1v[ii] = g_zn[m0 + ACC_ROW(ii)];

    float bestd[8];
    int   besti[8];
#pragma unroll
    for (int i = 0; i < 8; i++) { bestd[i] = 3.4e38f; besti[i] = 0; }

#pragma unroll 1
    for (int c0 = 0; c0 < 1024; c0 += 128) {
        float acc[8][16];
#pragma unroll
        for (int i = 0; i < 8; i++)
#pragma unroll
            for (int j = 0; j < 16; j++) acc[i][j] = 0.0f;

        gemm_sweep<L_E4, 512, 1024>(g_z, g_CBt, m0, c0, 0,
                                    As, Bs, tid, trow, tcol, brow, bcol, acc);
        __syncthreads();   // safe reuse of As/Bs next c0 iteration

        // candidates: per-thread scan in ascending code order => strict '<'
        // keeps the lowest index on ties (matches jnp.argmin)
#pragma unroll
        for (int jj = 0; jj < 16; jj++) {
            const int code = c0 + ACC_COL(jj);
            const float cn = g_cbn[code];
#pragma unroll
            for (int ii = 0; ii < 8; ii++) {
                // replicate: t = fl(s1 + s2); d = fl(t - 2p)  (2p exact; FMA = single round)
                float t = __fadd_rn(s1v[ii], cn);
                float d = __fmaf_rn(-2.0f, acc[ii][jj], t);
                if (d < bestd[ii]) { bestd[ii] = d; besti[ii] = code; }
            }
        }
    }

#pragma unroll
    for (int ii = 0; ii < 8; ii++) {
        const int r = ACC_ROW(ii);
        sd[r][tcol] = bestd[ii];
        si[r][tcol] = besti[ii];
    }
    __syncthreads();
    // one thread per row: combine 8 column-owners (lowest code wins on ties)
    {
        float bd = sd[tid][0];
        int   bi = si[tid][0];
#pragma unroll
        for (int t = 1; t < 8; t++) {
            float d = sd[tid][t];
            int   ii = si[tid][t];
            if (d < bd || (d == bd && ii < bi)) { bd = d; bi = ii; }
        }
        g_idx[m0 + tid] = bi;
    }
}

// ---------------------------------------------------------------------------
// gather z_q_st = fl(z + fl(zq - z)) into output + accumulate ||z_q - z||^2
// ---------------------------------------------------------------------------
__global__ void gather_loss_kernel(const float* __restrict__ cb, float* __restrict__ zq_out)
{
    float lsum = 0.0f;
    for (int e = blockIdx.x * blockDim.x + threadIdx.x; e < NB * 512; e += gridDim.x * blockDim.x) {
        int n = e >> 9, k = e & 511;
        float zv = g_z[e];
        float cv = cb[g_idx[n] * 512 + k];
        float diff = __fadd_rn(cv, -zv);           // fl(zq - z)
        zq_out[e] = __fadd_rn(zv, diff);           // fl(z + fl(zq - z))  == z_q_st
        lsum = fmaf(diff, diff, lsum);
    }
    __shared__ float red[256];
    red[threadIdx.x] = lsum;
    __syncthreads();
    for (int s = 128; s > 0; s >>= 1) {
        if ((int)threadIdx.x < s) red[threadIdx.x] += red[threadIdx.x + s];
        __syncthreads();
    }
    if (threadIdx.x == 0) atomicAdd(&g_loss, (double)red[0]);
}

__global__ void yinit_kernel(const float* __restrict__ db3)
{
    for (int e = blockIdx.x * blockDim.x + threadIdx.x; e < NB * 1280; e += gridDim.x * blockDim.x) {
        int r = e % 1280;
        g_y[e] = db3[r / 10];
    }
}

__global__ void finalize_kernel(float* __restrict__ out)
{
    int n = blockIdx.x * blockDim.x + threadIdx.x;
    if (n < NB) out[IDX_OFF + n] = (float)g_idx[n];
    if (n == 0) {
        out[EMB_OFF]     = (float)(1.25 * (g_loss / 8388608.0));
        out[EMB_OFF + 1] = 0.0f;
        out[EMB_OFF + 2] = 0.0f;
    }
}

// ---------------------------------------------------------------------------
extern "C" void kernel_launch(void* const* d_in, const int* in_sizes, int n_in,
                              void* d_out, int out_size)
{
    (void)in_sizes; (void)n_in; (void)out_size;
    const float* x   = (const float*)d_in[0];
    const float* cb  = (const float*)d_in[1];
    const float* ew1 = (const float*)d_in[2];
    const float* eb1 = (const float*)d_in[3];
    const float* ew2 = (const float*)d_in[4];
    const float* eb2 = (const float*)d_in[5];
    const float* ew3 = (const float*)d_in[6];
    const float* eb3 = (const float*)d_in[7];
    const float* ew4 = (const float*)d_in[8];
    const float* eb4 = (const float*)d_in[9];
    const float* dw1 = (const float*)d_in[10];
    const float* db1 = (const float*)d_in[11];
    const float* dw2 = (const float*)d_in[12];
    const float* db2 = (const float*)d_in[13];
    const float* dw3 = (const float*)d_in[14];
    const float* db3 = (const float*)d_in[15];
    const float* dw4 = (const float*)d_in[16];
    const float* db4 = (const float*)d_in[17];
    float* out = (float*)d_out;

    prep_kernel<<<2048, 256>>>(ew1, ew2, ew3, ew4, cb, dw2);

    gemm_k<L_E1><<<dim3(1, 1280), 128>>>(x, nullptr, eb1, nullptr, 0);
    gemm_k<L_E2><<<dim3(2, 512),  128>>>(nullptr, nullptr, eb2, nullptr, 0);
    gemm_k<L_E3><<<dim3(4, 128),  128>>>(nullptr, nullptr, eb3, nullptr, 0);
    gemm_k<L_E4><<<dim3(4, 128),  128>>>(nullptr, nullptr, eb4, nullptr, 0);

    rownorm_kernel<<<NB / 8, 256>>>();
    vq_kernel<<<128, 128>>>();
    gather_loss_kernel<<<2048, 256>>>(cb, out + ZQ_OFF);
    finalize_kernel<<<64, 256>>>(out);

    gemm_k<L_D1><<<dim3(4, 128), 128>>>(out + ZQ_OFF, dw1, db1, nullptr, 0);
    gemm_k<L_D2><<<dim3(8, 128), 128>>>(nullptr, nullptr, db2, nullptr, 0);
    yinit_kernel<<<2048, 256>>>(db3);
    for (int s = 0; s < 4; s++)
        gemm_k<L_D3><<<dim3(4, 128), 128>>>(nullptr, dw3, nullptr, nullptr, s);
    gemm_k<L_D4><<<dim3(2, 1280), 128>>>(nullptr, dw4, db4, out + XHAT_OFF, 0);
}

// round 6
// speedup vs baseline: 1.2771x; 1.2771x over previous
#include <cuda_runtime.h>
#include <cstdint>

#define NB 16384

enum { L_E1 = 0, L_E2, L_E3, L_E4, L_D1, L_D2, L_D3, L_D4 };

// Output layout (concatenated flat outputs, float32):
//   zq3   : [0, 8388608)            (N,512,1)
//   x_hat : [8388608, 50331648)     (N,256,10)
//   idx   : [50331648, 50348032)    (N,1) as float
//   emb_loss, qq_loss, ac_loss : 3 scalars
#define ZQ_OFF   0
#define XHAT_OFF 8388608
#define IDX_OFF  50331648
#define EMB_OFF  50348032

// ---- scratch (device globals; no allocation allowed) ----
__device__ float g_h1[NB * 1280];   // (N,10,128) encoder conv1 out (post-relu)
__device__ float g_h2[NB * 1024];   // (N,4,256)  encoder conv2 out (post-relu)
__device__ float g_h3[NB * 512];    // (N,512)    encoder conv3 out (post-relu)
__device__ float g_z [NB * 512];    // (N,512)    z_e
__device__ float g_zn[NB];          // |z|^2 per row, correctly-rounded fp32
__device__ float g_d1[NB * 512];    // (N,512)    decoder convT1 out (post-relu)
__device__ float g_d2[NB * 1024];   // (N, s(4), i(256)) decoder convT2 out (post-relu)
__device__ float g_y [NB * 1280];   // (N, o(128), t(10)) convT3 accumulator (pre-relu)
__device__ int   g_idx[NB];

// transformed weights: uniform [K][N] layout
__device__ float g_W1t[256 * 128];
__device__ float g_W2t[512 * 256];
__device__ float g_W3t[1024 * 512];
__device__ float g_W4t[512 * 512];
__device__ float g_V2t[512 * 1024];
__device__ float g_CBt[512 * 1024]; // codebook transposed (k, e)
__device__ float g_cbn[1024];       // |e|^2 (fp64-accumulated, rounded to fp32)
__device__ double g_loss;

// ---------------------------------------------------------------------------
// weight pre-transforms (cheap, a few MB, run every launch)
// ---------------------------------------------------------------------------
__global__ void prep_kernel(const float* __restrict__ ew1, const float* __restrict__ ew2,
                            const float* __restrict__ ew3, const float* __restrict__ ew4,
                            const float* __restrict__ cb,  const float* __restrict__ dw2)
{
    int e = blockIdx.x * blockDim.x + threadIdx.x;   // 524288 threads
    if (e < 256 * 128)  { int k = e >> 7,  o = e & 127;  g_W1t[e] = ew1[o * 256 + k]; }
    if (e < 512 * 256)  { int k = e >> 8,  o = e & 255;  g_W2t[e] = ew2[o * 512 + (k & 127) * 4 + (k >> 7)]; }
    if (e < 1024 * 512) { int k = e >> 9,  o = e & 511;  g_W3t[e] = ew3[o * 1024 + (k & 255) * 4 + (k >> 8)]; }
    if (e < 512 * 512)  { int k = e >> 9,  o = e & 511;  g_W4t[e] = ew4[o * 512 + k]; }
    if (e < 512 * 1024) { int k = e >> 10, c = e & 1023; g_CBt[e] = cb[c * 512 + k]; }
    if (e < 512 * 1024) { int k = e >> 10, j = e & 1023; g_V2t[e] = dw2[k * 1024 + (j & 255) * 4 + (j >> 8)]; }
    if (e < 1024) {
        double s = 0.0;
        for (int k = 0; k < 512; k++) { float v = cb[e * 512 + k]; s += (double)(v * v); }
        g_cbn[e] = (float)s;
    }
    if (e == 0) g_loss = 0.0;
}

// ---------------------------------------------------------------------------
// per-row |z|^2: fp32 squares, fp64 accumulate, single rounding to fp32
// ---------------------------------------------------------------------------
__global__ void rownorm_kernel()
{
    int warp = (blockIdx.x * blockDim.x + threadIdx.x) >> 5;  // one warp per row
    int lane = threadIdx.x & 31;
    if (warp >= NB) return;
    const float* zr = g_z + warp * 512;
    double s = 0.0;
    for (int k = lane; k < 512; k += 32) {
        float v = zr[k];
        s += (double)(v * v);
    }
#pragma unroll
    for (int o = 16; o > 0; o >>= 1)
        s += __shfl_down_sync(0xffffffffu, s, o);
    if (lane == 0) g_zn[warp] = (float)s;
}

// ---------------------------------------------------------------------------
// per-layer A-tile element loads (im2col folded in)
// ---------------------------------------------------------------------------
template <int L>
__device__ __forceinline__ float ldA(const float* __restrict__ A, int m, int k, int sarg)
{
    if constexpr (L == L_E1) {           // x (N,256,10), m = n*10+t
        int n = m / 10, t = m - n * 10;
        return A[n * 2560 + k * 10 + t];
    } else if constexpr (L == L_E2) {    // h1 (N,10,128), m = n*4+s, k = kk*128+i
        int n = m >> 2, s = m & 3;
        return A[(n * 10 + 2 * s + (k >> 7)) * 128 + (k & 127)];
    } else if constexpr (L == L_E3) {
        return A[m * 1024 + k];
    } else if constexpr (L == L_D3) {    // d2 (N, s, i): slice sarg
        return A[m * 1024 + sarg * 256 + k];
    } else if constexpr (L == L_D4) {    // y (N,o,t) with deferred relu, m = n*10+t, k = o
        int n = m / 10, t = m - n * 10;
        return fmaxf(A[n * 1280 + k * 10 + t], 0.0f);
    } else {                             // E4, D1, D2: (N,512)
        return A[m * 512 + k];
    }
}

// ===========================================================================
// R3 fp32 SGEMM core (encoder + VQ — must stay bit-identical):
// 128x128 block, BK=8, 256 threads, split 2x2 of 4x4 frags,
// float4 smem fragments, register-prefetch double buffering.
// ===========================================================================
#define GEMM_CORE_DECLS                                                        \
    __shared__ float As[2][8][128];                                            \
    __shared__ float Bs[2][8][128];                                            \
    const int tid  = threadIdx.x;                                              \
    const int tr2  = (tid >> 4) * 4;                                           \
    const int tc2  = (tid & 15) * 4;                                           \
    const int ml   = tid & 127;                                                \
    const int kA   = tid >> 7;   /* 0/1 */                                     \
    const int brow = tid >> 5;   /* 0..7 */                                    \
    const int bcol = (tid & 31) * 4;

template <int L, int K, int NT>
__device__ __forceinline__ void gemm_sweep(
    const float* __restrict__ A, const float* __restrict__ B,
    int m0, int n0, int sarg,
    float As[2][8][128], float Bs[2][8][128],
    int tid, int tr2, int tc2, int ml, int kA, int brow, int bcol,
    float acc[8][8])
{
#pragma unroll
    for (int i = 0; i < 4; i++)
        As[0][2 * i + kA][ml] = ldA<L>(A, m0 + ml, 2 * i + kA, sarg);
    *(float4*)&Bs[0][brow][bcol] = *(const float4*)&B[brow * NT + n0 + bcol];
    __syncthreads();

    int buf = 0;
#pragma unroll 1
    for (int k0 = 0; k0 < K; k0 += 8) {
        float  ar[4];
        float4 br;
        const bool more = (k0 + 8 < K);
        if (more) {
#pragma unroll
            for (int i = 0; i < 4; i++)
                ar[i] = ldA<L>(A, m0 + ml, k0 + 8 + 2 * i + kA, sarg);
            br = *(const float4*)&B[(k0 + 8 + brow) * NT + n0 + bcol];
        }
#pragma unroll
        for (int kk = 0; kk < 8; kk++) {
            float a[8], b[8];
            *(float4*)&a[0] = *(const float4*)&As[buf][kk][tr2];
            *(float4*)&a[4] = *(const float4*)&As[buf][kk][tr2 + 64];
            *(float4*)&b[0] = *(const float4*)&Bs[buf][kk][tc2];
            *(float4*)&b[4] = *(const float4*)&Bs[buf][kk][tc2 + 64];
#pragma unroll
            for (int ii = 0; ii < 8; ii++)
#pragma unroll
                for (int jj = 0; jj < 8; jj++)
                    acc[ii][jj] = fmaf(a[ii], b[jj], acc[ii][jj]);
        }
        if (more) {
#pragma unroll
            for (int i = 0; i < 4; i++)
                As[buf ^ 1][2 * i + kA][ml] = ar[i];
            *(float4*)&Bs[buf ^ 1][brow][bcol] = br;
            __syncthreads();
            buf ^= 1;
        }
    }
}

// ---------------------------------------------------------------------------
// encoder fp32 SGEMM with per-layer epilogue (E1..E4 only launched)
// ---------------------------------------------------------------------------
template <int L>
__global__ __launch_bounds__(256, 2)
void gemm_k(const float* __restrict__ extA, const float* __restrict__ extB,
            const float* __restrict__ bias, float* __restrict__ extC, int sarg)
{
    constexpr int K  = (L == L_E1) ? 256 : (L == L_E2) ? 512 : (L == L_E3) ? 1024 : 512;
    constexpr int NT = (L == L_E1) ? 128 : (L == L_E2) ? 256 : (L == L_E3) ? 512 : 512;

    const float* A = extA;
    const float* B = extB;
    float* C = extC;
    if constexpr (L == L_E1) { B = g_W1t; C = g_h1; }
    if constexpr (L == L_E2) { A = g_h1; B = g_W2t; C = g_h2; }
    if constexpr (L == L_E3) { A = g_h2; B = g_W3t; C = g_h3; }
    if constexpr (L == L_E4) { A = g_h3; B = g_W4t; C = g_z; }

    GEMM_CORE_DECLS
    const int m0 = blockIdx.y * 128;
    const int n0 = blockIdx.x * 128;

    float acc[8][8];
#pragma unroll
    for (int i = 0; i < 8; i++)
#pragma unroll
        for (int j = 0; j < 8; j++) acc[i][j] = 0.0f;

    gemm_sweep<L, K, NT>(A, B, m0, n0, sarg, As, Bs, tid, tr2, tc2, ml, kA, brow, bcol, acc);

#pragma unroll
    for (int ii = 0; ii < 8; ii++) {
        const int m = m0 + tr2 + (ii & 3) + ((ii & 4) ? 64 : 0);
#pragma unroll
        for (int jj = 0; jj < 8; jj++) {
            const int col = n0 + tc2 + (jj & 3) + ((jj & 4) ? 64 : 0);
            float v = acc[ii][jj] + bias[col];
            if constexpr (L != L_E4) v = fmaxf(v, 0.0f);  // E1..E3 relu
            C[m * NT + col] = v;
        }
    }
}

// ---------------------------------------------------------------------------
// VQ: per-row argmin of d = fl( fl(|z|^2 + |e|^2) - 2 z.e )  — exact fp32
// replication of the reference's rounding so near-tie resolution matches.
// ---------------------------------------------------------------------------
__global__ __launch_bounds__(256, 2)
void vq_kernel()
{
    GEMM_CORE_DECLS
    __shared__ float sd[128][16];
    __shared__ int   si[128][16];

    const int m0 = blockIdx.x * 128;

    float s1v[8];
#pragma unroll
    for (int ii = 0; ii < 8; ii++)
        s1v[ii] = g_zn[m0 + tr2 + (ii & 3) + ((ii & 4) ? 64 : 0)];

    float bestd[8];
    int   besti[8];
#pragma unroll
    for (int i = 0; i < 8; i++) { bestd[i] = 3.4e38f; besti[i] = 0; }

#pragma unroll 1
    for (int c0 = 0; c0 < 1024; c0 += 128) {
        float acc[8][8];
#pragma unroll
        for (int i = 0; i < 8; i++)
#pragma unroll
            for (int j = 0; j < 8; j++) acc[i][j] = 0.0f;

        gemm_sweep<L_E4, 512, 1024>(g_z, g_CBt, m0, c0, 0,
                                    As, Bs, tid, tr2, tc2, ml, kA, brow, bcol, acc);
        __syncthreads();   // safe reuse of As/Bs next c0 iteration

        // candidates (ascending code order within thread => strict '<' keeps first min)
#pragma unroll
        for (int jj = 0; jj < 8; jj++) {
            const int code = c0 + tc2 + (jj & 3) + ((jj & 4) ? 64 : 0);
            const float cn = g_cbn[code];
#pragma unroll
            for (int ii = 0; ii < 8; ii++) {
                // replicate: t = fl(s1 + s2); d = fl(t - 2p)  (2p exact; FMA = single round)
                float t = __fadd_rn(s1v[ii], cn);
                float d = __fmaf_rn(-2.0f, acc[ii][jj], t);
                if (d < bestd[ii]) { bestd[ii] = d; besti[ii] = code; }
            }
        }
    }

#pragma unroll
    for (int ii = 0; ii < 8; ii++) {
        const int r = tr2 + (ii & 3) + ((ii & 4) ? 64 : 0);
        sd[r][tid & 15] = bestd[ii];
        si[r][tid & 15] = besti[ii];
    }
    __syncthreads();
    if (tid < 128) {
        float bd = sd[tid][0];
        int   bi = si[tid][0];
#pragma unroll
        for (int t = 1; t < 16; t++) {
            float d = sd[tid][t];
            int   ii = si[tid][t];
            if (d < bd || (d == bd && ii < bi)) { bd = d; bi = ii; }
        }
        g_idx[m0 + tid] = bi;
    }
}

// ===========================================================================
// Decoder: tensor-core GEMM (3xTF32, mma.sync m16n8k8) — x_hat path only.
// 128x128 CTA tile, 256 thr = 8 warps (2x4), warp tile 64x32, BK=8,
// double-buffered smem with hi/lo operands pre-permuted into fragment order.
// ===========================================================================
__device__ __forceinline__ unsigned tf32_of(float x)
{
    unsigned r;
    asm("cvt.rna.tf32.f32 %0, %1;" : "=r"(r) : "f"(x));
    return r;
}

#define MMA_TF32(c, a, b0, b1)                                                  \
    asm("mma.sync.aligned.m16n8k8.row.col.f32.tf32.tf32.f32 "                  \
        "{%0,%1,%2,%3}, {%4,%5,%6,%7}, {%8,%9}, {%0,%1,%2,%3};"                \
        : "+f"((c)[0]), "+f"((c)[1]), "+f"((c)[2]), "+f"((c)[3])               \
        : "r"((a).x), "r"((a).y), "r"((a).z), "r"((a).w), "r"(b0), "r"(b1))

template <int L>
__global__ __launch_bounds__(256, 1)
void tc_gemm_k(const float* __restrict__ extA, const float* __restrict__ extB,
               const float* __restrict__ bias, float* __restrict__ extC, int sarg)
{
    constexpr int K  = (L == L_D1) ? 512 : (L == L_D2) ? 512 : (L == L_D3) ? 256 : 128;
    constexpr int NT = (L == L_D1) ? 512 : (L == L_D2) ? 1024 : (L == L_D3) ? 512 : 256;

    const float* A = extA;
    const float* B = extB;
    float* C = extC;
    if constexpr (L == L_D1) { C = g_d1; }
    if constexpr (L == L_D2) { A = g_d1; B = g_V2t; C = g_d2; }
    if constexpr (L == L_D3) { A = g_d2; C = g_y; }
    if constexpr (L == L_D4) { A = g_y; }

    // fragment-order smem: [stage][tile(8)][lane(32)] each uint4 = lane's 4 regs
    __shared__ uint4 AH[2][8][32], AL[2][8][32], BH[2][8][32], BL[2][8][32];

    const int tid    = threadIdx.x;
    const int lane   = tid & 31;
    const int seg    = tid >> 5;        // 0..7  (loader segment == warp id)
    const int warp_m = seg >> 2;        // 0..1
    const int warp_n = seg & 3;         // 0..3

    const int m0 = blockIdx.y * 128;
    const int n0 = blockIdx.x * 128;

    float acc[4][4][4];
#pragma unroll
    for (int a = 0; a < 4; a++)
#pragma unroll
        for (int b = 0; b < 4; b++)
#pragma unroll
            for (int c = 0; c < 4; c++) acc[a][b][c] = 0.0f;

    // A loader: tile t = seg; reg rg: row r = (lane>>2)+8*(rg&1), k = (lane&3)+4*(rg>>1)
    auto loadAvals = [&](int k0, float av[4]) {
#pragma unroll
        for (int rg = 0; rg < 4; rg++) {
            int r  = (lane >> 2) + 8 * (rg & 1);
            int kk = (lane & 3) + 4 * (rg >> 1);
            av[rg] = ldA<L>(A, m0 + 16 * seg + r, k0 + kk, sarg);
        }
    };
    // B loader: pair u2 = seg; reg rg: n = 16*u2 + 8*(rg>>1) + (lane>>2), k = (lane&3)+4*(rg&1)
    auto loadBvals = [&](int k0, float bv[4]) {
#pragma unroll
        for (int rg = 0; rg < 4; rg++) {
            int n  = n0 + 16 * seg + 8 * (rg >> 1) + (lane >> 2);
            int kk = (lane & 3) + 4 * (rg & 1);
            bv[rg] = B[(k0 + kk) * NT + n];
        }
    };
    auto stsTile = [&](int st, const float av[4], const float bv[4]) {
        uint4 ah, al, bh, bl;
        unsigned h;
        h = tf32_of(av[0]); ah.x = h; al.x = tf32_of(__fsub_rn(av[0], __uint_as_float(h)));
        h = tf32_of(av[1]); ah.y = h; al.y = tf32_of(__fsub_rn(av[1], __uint_as_float(h)));
        h = tf32_of(av[2]); ah.z = h; al.z = tf32_of(__fsub_rn(av[2], __uint_as_float(h)));
        h = tf32_of(av[3]); ah.w = h; al.w = tf32_of(__fsub_rn(av[3], __uint_as_float(h)));
        h = tf32_of(bv[0]); bh.x = h; bl.x = tf32_of(__fsub_rn(bv[0], __uint_as_float(h)));
        h = tf32_of(bv[1]); bh.y = h; bl.y = tf32_of(__fsub_rn(bv[1], __uint_as_float(h)));
        h = tf32_of(bv[2]); bh.z = h; bl.z = tf32_of(__fsub_rn(bv[2], __uint_as_float(h)));
        h = tf32_of(bv[3]); bh.w = h; bl.w = tf32_of(__fsub_rn(bv[3], __uint_as_float(h)));
        AH[st][seg][lane] = ah; AL[st][seg][lane] = al;
        BH[st][seg][lane] = bh; BL[st][seg][lane] = bl;
    };
    auto computeTile = [&](int st) {
        uint4 ah[4], al[4];
#pragma unroll
        for (int mt = 0; mt < 4; mt++) {
            ah[mt] = AH[st][warp_m * 4 + mt][lane];
            al[mt] = AL[st][warp_m * 4 + mt][lane];
        }
#pragma unroll
        for (int p = 0; p < 2; p++) {
            uint4 bh = BH[st][warp_n * 2 + p][lane];
            uint4 bl = BL[st][warp_n * 2 + p][lane];
#pragma unroll
            for (int mt = 0; mt < 4; mt++) {
#pragma unroll
                for (int sub = 0; sub < 2; sub++) {
                    const int nt = 2 * p + sub;
                    unsigned b0h = sub ? bh.z : bh.x, b1h = sub ? bh.w : bh.y;
                    unsigned b0l = sub ? bl.z : bl.x, b1l = sub ? bl.w : bl.y;
                    float* c = acc[mt][nt];
                    MMA_TF32(c, al[mt], b0h, b1h);   // lo_a * hi_b
                    MMA_TF32(c, ah[mt], b0l, b1l);   // hi_a * lo_b
                    MMA_TF32(c, ah[mt], b0h, b1h);   // hi_a * hi_b
                }
            }
        }
    };

    float av[4], bv[4];
    loadAvals(0, av);
    loadBvals(0, bv);
    stsTile(0, av, bv);
    __syncthreads();

    int buf = 0;
#pragma unroll 1
    for (int k0 = 0; k0 < K; k0 += 8) {
        const bool more = (k0 + 8 < K);
        if (more) { loadAvals(k0 + 8, av); loadBvals(k0 + 8, bv); }
        computeTile(buf);
        if (more) {
            stsTile(buf ^ 1, av, bv);
            __syncthreads();
            buf ^= 1;
        }
    }

    // epilogue: c0=(r,c) c1=(r,c+1) c2=(r+8,c) c3=(r+8,c+1)
#pragma unroll
    for (int mt = 0; mt < 4; mt++) {
#pragma unroll
        for (int nt = 0; nt < 4; nt++) {
#pragma unroll
            for (int q = 0; q < 4; q++) {
                const int m   = m0 + warp_m * 64 + 16 * mt + (lane >> 2) + ((q & 2) ? 8 : 0);
                const int col = n0 + warp_n * 32 + 8 * nt + 2 * (lane & 3) + (q & 1);
                float v = acc[mt][nt][q];
                if constexpr (L == L_D3) {
                    // scatter-add into y (N, o, t): col = o*4 + kk, t = 2s + kk
                    C[m * 1280 + (col >> 2) * 10 + 2 * sarg + (col & 3)] += v;
                } else if constexpr (L == L_D4) {
                    int n = m / 10, t = m - n * 10;
                    C[n * 2560 + col * 10 + t] = v + bias[col];
                } else {
                    v += bias[(L == L_D2) ? (col & 255) : col];
                    v = fmaxf(v, 0.0f);   // D1, D2 relu
                    C[m * NT + col] = v;
                }
            }
        }
    }
}

// ---------------------------------------------------------------------------
// gather z_q_st = fl(z + fl(zq - z)) into output + accumulate ||z_q - z||^2
// ---------------------------------------------------------------------------
__global__ void gather_loss_kernel(const float* __restrict__ cb, float* __restrict__ zq_out)
{
    float lsum = 0.0f;
    for (int e = blockIdx.x * blockDim.x + threadIdx.x; e < NB * 512; e += gridDim.x * blockDim.x) {
        int n = e >> 9, k = e & 511;
        float zv = g_z[e];
        float cv = cb[g_idx[n] * 512 + k];
        float diff = __fadd_rn(cv, -zv);           // fl(zq - z)
        zq_out[e] = __fadd_rn(zv, diff);           // fl(z + fl(zq - z))  == z_q_st
        lsum = fmaf(diff, diff, lsum);
    }
    __shared__ float red[256];
    red[threadIdx.x] = lsum;
    __syncthreads();
    for (int s = 128; s > 0; s >>= 1) {
        if ((int)threadIdx.x < s) red[threadIdx.x] += red[threadIdx.x + s];
        __syncthreads();
    }
    if (threadIdx.x == 0) atomicAdd(&g_loss, (double)red[0]);
}

__global__ void yinit_kernel(const float* __restrict__ db3)
{
    for (int e = blockIdx.x * blockDim.x + threadIdx.x; e < NB * 1280; e += gridDim.x * blockDim.x) {
        int r = e % 1280;
        g_y[e] = db3[r / 10];
    }
}

__global__ void finalize_kernel(float* __restrict__ out)
{
    int n = blockIdx.x * blockDim.x + threadIdx.x;
    if (n < NB) out[IDX_OFF + n] = (float)g_idx[n];
    if (n == 0) {
        out[EMB_OFF]     = (float)(1.25 * (g_loss / 8388608.0));
        out[EMB_OFF + 1] = 0.0f;
        out[EMB_OFF + 2] = 0.0f;
    }
}

// ---------------------------------------------------------------------------
extern "C" void kernel_launch(void* const* d_in, const int* in_sizes, int n_in,
                              void* d_out, int out_size)
{
    (void)in_sizes; (void)n_in; (void)out_size;
    const float* x   = (const float*)d_in[0];
    const float* cb  = (const float*)d_in[1];
    const float* ew1 = (const float*)d_in[2];
    const float* eb1 = (const float*)d_in[3];
    const float* ew2 = (const float*)d_in[4];
    const float* eb2 = (const float*)d_in[5];
    const float* ew3 = (const float*)d_in[6];
    const float* eb3 = (const float*)d_in[7];
    const float* ew4 = (const float*)d_in[8];
    const float* eb4 = (const float*)d_in[9];
    const float* dw1 = (const float*)d_in[10];
    const float* db1 = (const float*)d_in[11];
    const float* dw2 = (const float*)d_in[12];
    const float* db2 = (const float*)d_in[13];
    const float* dw3 = (const float*)d_in[14];
    const float* db3 = (const float*)d_in[15];
    const float* dw4 = (const float*)d_in[16];
    const float* db4 = (const float*)d_in[17];
    float* out = (float*)d_out;

    prep_kernel<<<2048, 256>>>(ew1, ew2, ew3, ew4, cb, dw2);

    // encoder: exact fp32 SIMT (argmin-critical path)
    gemm_k<L_E1><<<dim3(1, 1280), 256>>>(x, nullptr, eb1, nullptr, 0);
    gemm_k<L_E2><<<dim3(2, 512),  256>>>(nullptr, nullptr, eb2, nullptr, 0);
    gemm_k<L_E3><<<dim3(4, 128),  256>>>(nullptr, nullptr, eb3, nullptr, 0);
    gemm_k<L_E4><<<dim3(4, 128),  256>>>(nullptr, nullptr, eb4, nullptr, 0);

    rownorm_kernel<<<NB / 8, 256>>>();
    vq_kernel<<<128, 256>>>();
    gather_loss_kernel<<<2048, 256>>>(cb, out + ZQ_OFF);
    finalize_kernel<<<64, 256>>>(out);

    // decoder: tensor cores (3xTF32) — only x_hat depends on this
    tc_gemm_k<L_D1><<<dim3(4, 128), 256>>>(out + ZQ_OFF, dw1, db1, nullptr, 0);
    tc_gemm_k<L_D2><<<dim3(8, 128), 256>>>(nullptr, nullptr, db2, nullptr, 0);
    yinit_kernel<<<2048, 256>>>(db3);
    for (int s = 0; s < 4; s++)
        tc_gemm_k<L_D3><<<dim3(4, 128), 256>>>(nullptr, dw3, nullptr, nullptr, s);
    tc_gemm_k<L_D4><<<dim3(2, 1280), 256>>>(nullptr, dw4, db4, out + XHAT_OFF, 0);
}

// round 7
// speedup vs baseline: 1.3859x; 1.0852x over previous
#include <cuda_runtime.h>
#include <cstdint>

#define NB 16384

enum { L_E1 = 0, L_E2, L_E3, L_E4, L_D1, L_D2, L_D3, L_D4 };

// Output layout (concatenated flat outputs, float32)
#define ZQ_OFF   0
#define XHAT_OFF 8388608
#define IDX_OFF  50331648
#define EMB_OFF  50348032

// ---- scratch (device globals; no allocation allowed) ----
__device__ float g_h1[NB * 1280];   // (N,10,128) encoder conv1 out (post-relu)
__device__ float g_h2[NB * 1024];   // (N,4,256)  encoder conv2 out (post-relu)
__device__ float g_h3[NB * 512];    // (N,512)    encoder conv3 out (post-relu)
__device__ float g_z [NB * 512];    // (N,512)    z_e
__device__ float g_zn[NB];          // |z|^2 per row, correctly-rounded fp32
__device__ float g_y [NB * 1280];   // (N, o(128), t(10)) convT3 accumulator (pre-relu)
__device__ int   g_idx[NB];

// encoder weights, [K][N] layout (fp32 exact path)
__device__ float g_W1t[256 * 128];
__device__ float g_W2t[512 * 256];
__device__ float g_W3t[1024 * 512];
__device__ float g_W4t[512 * 512];
__device__ float g_CBt[512 * 1024]; // codebook transposed (k, e)
__device__ float g_cbn[1024];       // |e|^2 (fp64-accumulated, rounded to fp32)
__device__ double g_loss;

// decoder: pre-decomposed tf32 hi/lo pairs (float2 = {hi, lo})
__device__ float2 g_zq2[NB * 512];       // z_q_st decomposed          (D1 A)
__device__ float2 g_d1h[NB * 512];       // d1 post-relu decomposed    (D2 A)
__device__ float2 g_d2h[NB * 1024];      // d2 post-relu decomposed    (D3 A)
__device__ float2 g_y2 [NB * 1280];      // relu(y) decomposed, [m=n*10+t][o] (D4 A)
__device__ float2 g_Wd1[512 * 512];      // dw1 [k][n]
__device__ float2 g_Wd2[512 * 1024];     // transformed dw2 [k][n]
__device__ float2 g_Wd3[256 * 512];      // dw3 [k][n]
__device__ float2 g_Wd4[128 * 256];      // dw4 [k][n]

__device__ __forceinline__ unsigned tf32_of(float x)
{
    unsigned r;
    asm("cvt.rna.tf32.f32 %0, %1;" : "=r"(r) : "f"(x));
    return r;
}
__device__ __forceinline__ float2 hilo(float v)
{
    float h = __uint_as_float(tf32_of(v));
    float l = __uint_as_float(tf32_of(__fsub_rn(v, h)));
    return make_float2(h, l);
}

// ---------------------------------------------------------------------------
// weight pre-transforms
// ---------------------------------------------------------------------------
__global__ void prep_kernel(const float* __restrict__ ew1, const float* __restrict__ ew2,
                            const float* __restrict__ ew3, const float* __restrict__ ew4,
                            const float* __restrict__ cb,  const float* __restrict__ dw1,
                            const float* __restrict__ dw2, const float* __restrict__ dw3,
                            const float* __restrict__ dw4)
{
    int e = blockIdx.x * blockDim.x + threadIdx.x;   // 524288 threads
    if (e < 256 * 128)  { int k = e >> 7,  o = e & 127;  g_W1t[e] = ew1[o * 256 + k]; }
    if (e < 512 * 256)  { int k = e >> 8,  o = e & 255;  g_W2t[e] = ew2[o * 512 + (k & 127) * 4 + (k >> 7)]; }
    if (e < 1024 * 512) { int k = e >> 9,  o = e & 511;  g_W3t[e] = ew3[o * 1024 + (k & 255) * 4 + (k >> 8)]; }
    if (e < 512 * 512)  { int k = e >> 9,  o = e & 511;  g_W4t[e] = ew4[o * 512 + k]; }
    if (e < 512 * 1024) { int k = e >> 10, c = e & 1023; g_CBt[e] = cb[c * 512 + k]; }
    // decoder weights, decomposed
    if (e < 512 * 512)  g_Wd1[e] = hilo(dw1[e]);                                   // [k][n] native
    if (e < 512 * 1024) { int k = e >> 10, j = e & 1023;
                          g_Wd2[e] = hilo(dw2[k * 1024 + (j & 255) * 4 + (j >> 8)]); }
    if (e < 256 * 512)  g_Wd3[e] = hilo(dw3[e]);                                   // [k][n] native
    if (e < 128 * 256)  g_Wd4[e] = hilo(dw4[e]);                                   // [k][n] native
    if (e < 1024) {
        double s = 0.0;
        for (int k = 0; k < 512; k++) { float v = cb[e * 512 + k]; s += (double)(v * v); }
        g_cbn[e] = (float)s;
    }
    if (e == 0) g_loss = 0.0;
}

// ---------------------------------------------------------------------------
// per-row |z|^2: fp32 squares, fp64 accumulate, single rounding to fp32
// ---------------------------------------------------------------------------
__global__ void rownorm_kernel()
{
    int warp = (blockIdx.x * blockDim.x + threadIdx.x) >> 5;
    int lane = threadIdx.x & 31;
    if (warp >= NB) return;
    const float* zr = g_z + warp * 512;
    double s = 0.0;
    for (int k = lane; k < 512; k += 32) {
        float v = zr[k];
        s += (double)(v * v);
    }
#pragma unroll
    for (int o = 16; o > 0; o >>= 1)
        s += __shfl_down_sync(0xffffffffu, s, o);
    if (lane == 0) g_zn[warp] = (float)s;
}

// ---------------------------------------------------------------------------
// encoder A-tile element loads (im2col folded in)
// ---------------------------------------------------------------------------
template <int L>
__device__ __forceinline__ float ldA(const float* __restrict__ A, int m, int k, int sarg)
{
    if constexpr (L == L_E1) {           // x (N,256,10), m = n*10+t
        int n = m / 10, t = m - n * 10;
        return A[n * 2560 + k * 10 + t];
    } else if constexpr (L == L_E2) {    // h1 (N,10,128), m = n*4+s, k = kk*128+i
        int n = m >> 2, s = m & 3;
        return A[(n * 10 + 2 * s + (k >> 7)) * 128 + (k & 127)];
    } else if constexpr (L == L_E3) {
        return A[m * 1024 + k];
    } else {                             // E4: (N,512)
        return A[m * 512 + k];
    }
}

// ===========================================================================
// R3 fp32 SGEMM core (encoder + VQ — bit-exact path)
// ===========================================================================
#define GEMM_CORE_DECLS                                                        \
    __shared__ float As[2][8][128];                                            \
    __shared__ float Bs[2][8][128];                                            \
    const int tid  = threadIdx.x;                                              \
    const int tr2  = (tid >> 4) * 4;                                           \
    const int tc2  = (tid & 15) * 4;                                           \
    const int ml   = tid & 127;                                                \
    const int kA   = tid >> 7;                                                 \
    const int brow = tid >> 5;                                                 \
    const int bcol = (tid & 31) * 4;

template <int L, int K, int NT>
__device__ __forceinline__ void gemm_sweep(
    const float* __restrict__ A, const float* __restrict__ B,
    int m0, int n0, int sarg,
    float As[2][8][128], float Bs[2][8][128],
    int tid, int tr2, int tc2, int ml, int kA, int brow, int bcol,
    float acc[8][8])
{
#pragma unroll
    for (int i = 0; i < 4; i++)
        As[0][2 * i + kA][ml] = ldA<L>(A, m0 + ml, 2 * i + kA, sarg);
    *(float4*)&Bs[0][brow][bcol] = *(const float4*)&B[brow * NT + n0 + bcol];
    __syncthreads();

    int buf = 0;
#pragma unroll 1
    for (int k0 = 0; k0 < K; k0 += 8) {
        float  ar[4];
        float4 br;
        const bool more = (k0 + 8 < K);
        if (more) {
#pragma unroll
            for (int i = 0; i < 4; i++)
                ar[i] = ldA<L>(A, m0 + ml, k0 + 8 + 2 * i + kA, sarg);
            br = *(const float4*)&B[(k0 + 8 + brow) * NT + n0 + bcol];
        }
#pragma unroll
        for (int kk = 0; kk < 8; kk++) {
            float a[8], b[8];
            *(float4*)&a[0] = *(const float4*)&As[buf][kk][tr2];
            *(float4*)&a[4] = *(const float4*)&As[buf][kk][tr2 + 64];
            *(float4*)&b[0] = *(const float4*)&Bs[buf][kk][tc2];
            *(float4*)&b[4] = *(const float4*)&Bs[buf][kk][tc2 + 64];
#pragma unroll
            for (int ii = 0; ii < 8; ii++)
#pragma unroll
                for (int jj = 0; jj < 8; jj++)
                    acc[ii][jj] = fmaf(a[ii], b[jj], acc[ii][jj]);
        }
        if (more) {
#pragma unroll
            for (int i = 0; i < 4; i++)
                As[buf ^ 1][2 * i + kA][ml] = ar[i];
            *(float4*)&Bs[buf ^ 1][brow][bcol] = br;
            __syncthreads();
            buf ^= 1;
        }
    }
}

// ---------------------------------------------------------------------------
// encoder fp32 SGEMM (E1..E4)
// ---------------------------------------------------------------------------
template <int L>
__global__ __launch_bounds__(256, 2)
void gemm_k(const float* __restrict__ extA, const float* __restrict__ extB,
            const float* __restrict__ bias, float* __restrict__ extC, int sarg)
{
    constexpr int K  = (L == L_E1) ? 256 : (L == L_E2) ? 512 : (L == L_E3) ? 1024 : 512;
    constexpr int NT = (L == L_E1) ? 128 : (L == L_E2) ? 256 : (L == L_E3) ? 512 : 512;

    const float* A = extA;
    const float* B = extB;
    float* C = extC;
    if constexpr (L == L_E1) { B = g_W1t; C = g_h1; }
    if constexpr (L == L_E2) { A = g_h1; B = g_W2t; C = g_h2; }
    if constexpr (L == L_E3) { A = g_h2; B = g_W3t; C = g_h3; }
    if constexpr (L == L_E4) { A = g_h3; B = g_W4t; C = g_z; }

    GEMM_CORE_DECLS
    const int m0 = blockIdx.y * 128;
    const int n0 = blockIdx.x * 128;

    float acc[8][8];
#pragma unroll
    for (int i = 0; i < 8; i++)
#pragma unroll
        for (int j = 0; j < 8; j++) acc[i][j] = 0.0f;

    gemm_sweep<L, K, NT>(A, B, m0, n0, sarg, As, Bs, tid, tr2, tc2, ml, kA, brow, bcol, acc);

#pragma unroll
    for (int ii = 0; ii < 8; ii++) {
        const int m = m0 + tr2 + (ii & 3) + ((ii & 4) ? 64 : 0);
#pragma unroll
        for (int jj = 0; jj < 8; jj++) {
            const int col = n0 + tc2 + (jj & 3) + ((jj & 4) ? 64 : 0);
            float v = acc[ii][jj] + bias[col];
            if constexpr (L != L_E4) v = fmaxf(v, 0.0f);
            C[m * NT + col] = v;
        }
    }
}

// ---------------------------------------------------------------------------
// VQ: per-row argmin of d = fl( fl(|z|^2 + |e|^2) - 2 z.e )  — exact fp32
// ---------------------------------------------------------------------------
__global__ __launch_bounds__(256, 2)
void vq_kernel()
{
    GEMM_CORE_DECLS
    __shared__ float sd[128][16];
    __shared__ int   si[128][16];

    const int m0 = blockIdx.x * 128;

    float s1v[8];
#pragma unroll
    for (int ii = 0; ii < 8; ii++)
        s1v[ii] = g_zn[m0 + tr2 + (ii & 3) + ((ii & 4) ? 64 : 0)];

    float bestd[8];
    int   besti[8];
#pragma unroll
    for (int i = 0; i < 8; i++) { bestd[i] = 3.4e38f; besti[i] = 0; }

#pragma unroll 1
    for (int c0 = 0; c0 < 1024; c0 += 128) {
        float acc[8][8];
#pragma unroll
        for (int i = 0; i < 8; i++)
#pragma unroll
            for (int j = 0; j < 8; j++) acc[i][j] = 0.0f;

        gemm_sweep<L_E4, 512, 1024>(g_z, g_CBt, m0, c0, 0,
                                    As, Bs, tid, tr2, tc2, ml, kA, brow, bcol, acc);
        __syncthreads();

#pragma unroll
        for (int jj = 0; jj < 8; jj++) {
            const int code = c0 + tc2 + (jj & 3) + ((jj & 4) ? 64 : 0);
            const float cn = g_cbn[code];
#pragma unroll
            for (int ii = 0; ii < 8; ii++) {
                float t = __fadd_rn(s1v[ii], cn);
                float d = __fmaf_rn(-2.0f, acc[ii][jj], t);
                if (d < bestd[ii]) { bestd[ii] = d; besti[ii] = code; }
            }
        }
    }

#pragma unroll
    for (int ii = 0; ii < 8; ii++) {
        const int r = tr2 + (ii & 3) + ((ii & 4) ? 64 : 0);
        sd[r][tid & 15] = bestd[ii];
        si[r][tid & 15] = besti[ii];
    }
    __syncthreads();
    if (tid < 128) {
        float bd = sd[tid][0];
        int   bi = si[tid][0];
#pragma unroll
        for (int t = 1; t < 16; t++) {
            float d = sd[tid][t];
            int   ii = si[tid][t];
            if (d < bd || (d == bd && ii < bi)) { bd = d; bi = ii; }
        }
        g_idx[m0 + tid] = bi;
    }
}

// ===========================================================================
// Decoder tc GEMM v2: 3xTF32 m16n8k8, operands PRE-DECOMPOSED (no cvt in loop)
// 128x128 CTA, 256 thr = 8 warps (2x4), warp tile 64x32, BK=8, double-buffered
// fragment-order smem. A2: float2 [m][KS] (+koff), B2: float2 [k][NT].
// ===========================================================================
#define MMA_TF32(c, a, b0, b1)                                                  \
    asm("mma.sync.aligned.m16n8k8.row.col.f32.tf32.tf32.f32 "                  \
        "{%0,%1,%2,%3}, {%4,%5,%6,%7}, {%8,%9}, {%0,%1,%2,%3};"                \
        : "+f"((c)[0]), "+f"((c)[1]), "+f"((c)[2]), "+f"((c)[3])               \
        : "r"((a).x), "r"((a).y), "r"((a).z), "r"((a).w), "r"(b0), "r"(b1))

template <int L>
__global__ __launch_bounds__(256, 2)
void tc_gemm_k(const float* __restrict__ bias, float* __restrict__ extC, int sarg)
{
    constexpr int K  = (L == L_D1) ? 512 : (L == L_D2) ? 512 : (L == L_D3) ? 256 : 128;
    constexpr int NT = (L == L_D1) ? 512 : (L == L_D2) ? 1024 : (L == L_D3) ? 512 : 256;
    constexpr int KS = (L == L_D3) ? 1024 : K;   // A row stride (D3 slices)

    const float2* A2 = (L == L_D1) ? g_zq2 : (L == L_D2) ? g_d1h :
                       (L == L_D3) ? g_d2h : g_y2;
    const float2* B2 = (L == L_D1) ? g_Wd1 : (L == L_D2) ? g_Wd2 :
                       (L == L_D3) ? g_Wd3 : g_Wd4;
    const int koff = (L == L_D3) ? sarg * 256 : 0;
    float* C = extC;
    if constexpr (L == L_D3) C = g_y;

    __shared__ uint4 AH[2][8][32], AL[2][8][32], BH[2][8][32], BL[2][8][32];

    const int tid    = threadIdx.x;
    const int lane   = tid & 31;
    const int seg    = tid >> 5;
    const int warp_m = seg >> 2;
    const int warp_n = seg & 3;

    const int m0 = blockIdx.y * 128;
    const int n0 = blockIdx.x * 128;

    float acc[4][4][4];
#pragma unroll
    for (int a = 0; a < 4; a++)
#pragma unroll
        for (int b = 0; b < 4; b++)
#pragma unroll
            for (int c = 0; c < 4; c++) acc[a][b][c] = 0.0f;

    auto loadA = [&](int k0, float2 av[4]) {
#pragma unroll
        for (int rg = 0; rg < 4; rg++) {
            int r  = (lane >> 2) + 8 * (rg & 1);
            int kk = (lane & 3) + 4 * (rg >> 1);
            av[rg] = A2[(m0 + 16 * seg + r) * KS + koff + k0 + kk];
        }
    };
    auto loadB = [&](int k0, float2 bv[4]) {
#pragma unroll
        for (int rg = 0; rg < 4; rg++) {
            int n  = n0 + 16 * seg + 8 * (rg >> 1) + (lane >> 2);
            int kk = (lane & 3) + 4 * (rg & 1);
            bv[rg] = B2[(k0 + kk) * NT + n];
        }
    };
    auto stsTile = [&](int st, const float2 av[4], const float2 bv[4]) {
        uint4 ah = { __float_as_uint(av[0].x), __float_as_uint(av[1].x),
                     __float_as_uint(av[2].x), __float_as_uint(av[3].x) };
        uint4 al = { __float_as_uint(av[0].y), __float_as_uint(av[1].y),
                     __float_as_uint(av[2].y), __float_as_uint(av[3].y) };
        uint4 bh = { __float_as_uint(bv[0].x), __float_as_uint(bv[1].x),
                     __float_as_uint(bv[2].x), __float_as_uint(bv[3].x) };
        uint4 bl = { __float_as_uint(bv[0].y), __float_as_uint(bv[1].y),
                     __float_as_uint(bv[2].y), __float_as_uint(bv[3].y) };
        AH[st][seg][lane] = ah; AL[st][seg][lane] = al;
        BH[st][seg][lane] = bh; BL[st][seg][lane] = bl;
    };
    auto computeTile = [&](int st) {
#pragma unroll
        for (int mt = 0; mt < 4; mt++) {
            uint4 ah = AH[st][warp_m * 4 + mt][lane];
            uint4 al = AL[st][warp_m * 4 + mt][lane];
#pragma unroll
            for (int p = 0; p < 2; p++) {
                uint4 bh = BH[st][warp_n * 2 + p][lane];
                uint4 bl = BL[st][warp_n * 2 + p][lane];
#pragma unroll
                for (int sub = 0; sub < 2; sub++) {
                    const int nt = 2 * p + sub;
                    unsigned b0h = sub ? bh.z : bh.x, b1h = sub ? bh.w : bh.y;
                    unsigned b0l = sub ? bl.z : bl.x, b1l = sub ? bl.w : bl.y;
                    float* c = acc[mt][nt];
                    MMA_TF32(c, al, b0h, b1h);   // lo_a * hi_b
                    MMA_TF32(c, ah, b0l, b1l);   // hi_a * lo_b
                    MMA_TF32(c, ah, b0h, b1h);   // hi_a * hi_b
                }
            }
        }
    };

    float2 av[4], bv[4];
    loadA(0, av);
    loadB(0, bv);
    stsTile(0, av, bv);
    __syncthreads();

    int buf = 0;
#pragma unroll 1
    for (int k0 = 0; k0 < K; k0 += 8) {
        const bool more = (k0 + 8 < K);
        if (more) { loadA(k0 + 8, av); loadB(k0 + 8, bv); }
        computeTile(buf);
        if (more) {
            stsTile(buf ^ 1, av, bv);
            __syncthreads();
            buf ^= 1;
        }
    }

    // epilogue: c0=(r,c) c1=(r,c+1) c2=(r+8,c) c3=(r+8,c+1)
#pragma unroll
    for (int mt = 0; mt < 4; mt++) {
#pragma unroll
        for (int nt = 0; nt < 4; nt++) {
#pragma unroll
            for (int q = 0; q < 4; q++) {
                const int m   = m0 + warp_m * 64 + 16 * mt + (lane >> 2) + ((q & 2) ? 8 : 0);
                const int col = n0 + warp_n * 32 + 8 * nt + 2 * (lane & 3) + (q & 1);
                float v = acc[mt][nt][q];
                if constexpr (L == L_D1) {
                    v = fmaxf(v + bias[col], 0.0f);
                    g_d1h[m * 512 + col] = hilo(v);
                } else if constexpr (L == L_D2) {
                    v = fmaxf(v + bias[col & 255], 0.0f);
                    g_d2h[m * 1024 + col] = hilo(v);
                } else if constexpr (L == L_D3) {
                    C[m * 1280 + (col >> 2) * 10 + 2 * sarg + (col & 3)] += v;
                } else {  // D4 -> x_hat
                    int n = m / 10, t = m - n * 10;
                    C[n * 2560 + col * 10 + t] = v + bias[col];
                }
            }
        }
    }
}

// ---------------------------------------------------------------------------
// gather z_q_st into output (+ decomposed copy) + accumulate ||z_q - z||^2
// ---------------------------------------------------------------------------
__global__ void gather_loss_kernel(const float* __restrict__ cb, float* __restrict__ zq_out)
{
    float lsum = 0.0f;
    for (int e = blockIdx.x * blockDim.x + threadIdx.x; e < NB * 512; e += gridDim.x * blockDim.x) {
        int n = e >> 9, k = e & 511;
        float zv = g_z[e];
        float cv = cb[g_idx[n] * 512 + k];
        float diff = __fadd_rn(cv, -zv);           // fl(zq - z)
        float st   = __fadd_rn(zv, diff);          // fl(z + fl(zq - z)) == z_q_st
        zq_out[e] = st;
        g_zq2[e]  = hilo(st);
        lsum = fmaf(diff, diff, lsum);
    }
    __shared__ float red[256];
    red[threadIdx.x] = lsum;
    __syncthreads();
    for (int s = 128; s > 0; s >>= 1) {
        if ((int)threadIdx.x < s) red[threadIdx.x] += red[threadIdx.x + s];
        __syncthreads();
    }
    if (threadIdx.x == 0) atomicAdd(&g_loss, (double)red[0]);
}

__global__ void yinit_kernel(const float* __restrict__ db3)
{
    for (int e = blockIdx.x * blockDim.x + threadIdx.x; e < NB * 1280; e += gridDim.x * blockDim.x) {
        int r = e % 1280;
        g_y[e] = db3[r / 10];
    }
}

// relu + decompose y into [m = n*10+t][o] layout for D4's A
__global__ void yprep_kernel()
{
    for (int e = blockIdx.x * blockDim.x + threadIdx.x; e < NB * 1280; e += gridDim.x * blockDim.x) {
        int n = e / 1280, r = e - n * 1280;
        int o = r / 10, t = r - o * 10;
        float v = fmaxf(g_y[e], 0.0f);
        g_y2[(n * 10 + t) * 128 + o] = hilo(v);
    }
}

__global__ void finalize_kernel(float* __restrict__ out)
{
    int n = blockIdx.x * blockDim.x + threadIdx.x;
    if (n < NB) out[IDX_OFF + n] = (float)g_idx[n];
    if (n == 0) {
        out[EMB_OFF]     = (float)(1.25 * (g_loss / 8388608.0));
        out[EMB_OFF + 1] = 0.0f;
        out[EMB_OFF + 2] = 0.0f;
    }
}

// ---------------------------------------------------------------------------
extern "C" void kernel_launch(void* const* d_in, const int* in_sizes, int n_in,
                              void* d_out, int out_size)
{
    (void)in_sizes; (void)n_in; (void)out_size;
    const float* x   = (const float*)d_in[0];
    const float* cb  = (const float*)d_in[1];
    const float* ew1 = (const float*)d_in[2];
    const float* eb1 = (const float*)d_in[3];
    const float* ew2 = (const float*)d_in[4];
    const float* eb2 = (const float*)d_in[5];
    const float* ew3 = (const float*)d_in[6];
    const float* eb3 = (const float*)d_in[7];
    const float* ew4 = (const float*)d_in[8];
    const float* eb4 = (const float*)d_in[9];
    const float* dw1 = (const float*)d_in[10];
    const float* db1 = (const float*)d_in[11];
    const float* dw2 = (const float*)d_in[12];
    const float* db2 = (const float*)d_in[13];
    const float* dw3 = (const float*)d_in[14];
    const float* db3 = (const float*)d_in[15];
    const float* dw4 = (const float*)d_in[16];
    const float* db4 = (const float*)d_in[17];
    float* out = (float*)d_out;

    prep_kernel<<<2048, 256>>>(ew1, ew2, ew3, ew4, cb, dw1, dw2, dw3, dw4);

    // encoder: exact fp32 SIMT (argmin-critical path)
    gemm_k<L_E1><<<dim3(1, 1280), 256>>>(x, nullptr, eb1, nullptr, 0);
    gemm_k<L_E2><<<dim3(2, 512),  256>>>(nullptr, nullptr, eb2, nullptr, 0);
    gemm_k<L_E3><<<dim3(4, 128),  256>>>(nullptr, nullptr, eb3, nullptr, 0);
    gemm_k<L_E4><<<dim3(4, 128),  256>>>(nullptr, nullptr, eb4, nullptr, 0);

    rownorm_kernel<<<NB / 8, 256>>>();
    vq_kernel<<<128, 256>>>();
    gather_loss_kernel<<<2048, 256>>>(cb, out + ZQ_OFF);
    finalize_kernel<<<64, 256>>>(out);

    // decoder: tensor cores (3xTF32, pre-decomposed operands)
    tc_gemm_k<L_D1><<<dim3(4, 128), 256>>>(db1, nullptr, 0);
    tc_gemm_k<L_D2><<<dim3(8, 128), 256>>>(db2, nullptr, 0);
    yinit_kernel<<<2048, 256>>>(db3);
    for (int s = 0; s < 4; s++)
        tc_gemm_k<L_D3><<<dim3(4, 128), 256>>>(nullptr, nullptr, s);
    yprep_kernel<<<2048, 256>>>();
    tc_gemm_k<L_D4><<<dim3(2, 1280), 256>>>(db4, out + XHAT_OFF, 0);
}